// round 2
// baseline (speedup 1.0000x reference)
#include <cuda_runtime.h>
#include <cuda_bf16.h>

// 3D life-like CA step (26-neighbor count, periodic wrap) on a 384^3 float
// grid; output is only the first out_size (=64) cells of the flattened new
// grid, i.e. cells (x=0, y=0, z=0..63). We evaluate the rule at just those
// cells: 27 neighborhood loads each.
//
// Inputs (metadata order):
//   d_in[0] grid         float32 [384^3]
//   d_in[1] survive_mask bool -> delivered as int32 [27]   (harness upcasts bool)
//   d_in[2] birth_mask   bool -> delivered as int32 [27]
//   d_in[3] num_models   int32 scalar (unused; out_size gives the count)
// Output: float32 [out_size]

#define DIM 384

__global__ void ca_first_cells_kernel(const float* __restrict__ grid,
                                      const int* __restrict__ survive_mask,
                                      const int* __restrict__ birth_mask,
                                      float* __restrict__ out,
                                      int out_size) {
    int i = blockIdx.x * blockDim.x + threadIdx.x;
    if (i >= out_size) return;

    // flat row-major index -> (x, y, z)
    int z = i % DIM;
    int y = (i / DIM) % DIM;
    int x = i / (DIM * DIM);

    // periodic neighbor coordinates along each axis
    int xs[3], ys[3], zs[3];
    xs[0] = (x + DIM - 1) % DIM; xs[1] = x; xs[2] = (x + 1) % DIM;
    ys[0] = (y + DIM - 1) % DIM; ys[1] = y; ys[2] = (y + 1) % DIM;
    zs[0] = (z + DIM - 1) % DIM; zs[1] = z; zs[2] = (z + 1) % DIM;

    float s = 0.0f;
#pragma unroll
    for (int a = 0; a < 3; a++) {
        int xoff = xs[a] * DIM * DIM;
#pragma unroll
        for (int b = 0; b < 3; b++) {
            int xyoff = xoff + ys[b] * DIM;
#pragma unroll
            for (int c = 0; c < 3; c++) {
                s += __ldg(&grid[xyoff + zs[c]]);
            }
        }
    }

    float center = __ldg(&grid[(x * DIM + y) * DIM + z]);
    // 26-neighbor live count; grid is 0/1 floats so the sum is exact in fp32.
    int ci = (int)(s - center + 0.5f);
    if (ci < 0) ci = 0;
    if (ci > 26) ci = 26;

    bool live = center > 0.5f;
    int r = live ? survive_mask[ci] : birth_mask[ci];
    out[i] = (float)r;
}

extern "C" void kernel_launch(void* const* d_in, const int* in_sizes, int n_in,
                              void* d_out, int out_size) {
    const float* grid = (const float*)d_in[0];
    const int* survive_mask = (const int*)d_in[1];
    const int* birth_mask = (const int*)d_in[2];
    float* out = (float*)d_out;

    int threads = 64;
    int blocks = (out_size + threads - 1) / threads;
    ca_first_cells_kernel<<<blocks, threads>>>(grid, survive_mask, birth_mask, out, out_size);
}